// round 12
// baseline (speedup 1.0000x reference)
#include <cuda_runtime.h>
#include <cuda_bf16.h>
#include <math.h>
#include <stdint.h>

#define S_LEN 4096
#define IN_DIM 1024
#define NODE 512
#define NH 8
#define HD 64
#define NKB (S_LEN / 64)

typedef __nv_bfloat16 bf16;
typedef __nv_bfloat162 bf162;

// ---------------- device scratch ----------------
__device__ bf16    g_Xbf[S_LEN * IN_DIM];
__device__ bf16    g_Wqb[NODE * IN_DIM];
__device__ bf16    g_Wkb[NODE * IN_DIM];
__device__ bf16    g_Wvb[NODE * IN_DIM];
__device__ bf16    g_Wob[NODE * NODE];
__device__ bf16    g_Cbf[(size_t)S_LEN * S_LEN];  // contact bf16 * 0.125
__device__ uint8_t g_Q8[(size_t)S_LEN * NODE];    // Q e4m3 (scale folded)
__device__ uint8_t g_K8[(size_t)S_LEN * NODE];    // K e4m3
__device__ bf16    g_Vbf[(size_t)S_LEN * NODE];   // V bf16
__device__ bf16    g_Obf[NH * S_LEN * HD];
__device__ float   g_aug[S_LEN * NODE];

// ---------------- helpers ----------------
__device__ __forceinline__ void mma16816(float c[4], const unsigned a[4],
                                         unsigned b0, unsigned b1) {
    asm volatile(
        "mma.sync.aligned.m16n8k16.row.col.f32.bf16.bf16.f32 "
        "{%0,%1,%2,%3}, {%4,%5,%6,%7}, {%8,%9}, {%0,%1,%2,%3};\n"
        : "+f"(c[0]), "+f"(c[1]), "+f"(c[2]), "+f"(c[3])
        : "r"(a[0]), "r"(a[1]), "r"(a[2]), "r"(a[3]), "r"(b0), "r"(b1));
}
__device__ __forceinline__ void mma16832f8(float c[4], const unsigned a[4],
                                           unsigned b0, unsigned b1) {
    asm volatile(
        "mma.sync.aligned.m16n8k32.row.col.f32.e4m3.e4m3.f32 "
        "{%0,%1,%2,%3}, {%4,%5,%6,%7}, {%8,%9}, {%0,%1,%2,%3};\n"
        : "+f"(c[0]), "+f"(c[1]), "+f"(c[2]), "+f"(c[3])
        : "r"(a[0]), "r"(a[1]), "r"(a[2]), "r"(a[3]), "r"(b0), "r"(b1));
}
__device__ __forceinline__ unsigned pack_bf16(float x, float y) {
    unsigned r;
    asm("cvt.rn.bf16x2.f32 %0, %1, %2;" : "=r"(r) : "f"(y), "f"(x));
    return r;
}
__device__ __forceinline__ unsigned short pack_e4m3(float x, float y) {
    unsigned short r;
    asm("cvt.rn.satfinite.e4m3x2.f32 %0, %1, %2;" : "=h"(r) : "f"(y), "f"(x));
    return r;
}
__device__ __forceinline__ float ex2(float x) {
    float y;
    asm("ex2.approx.f32 %0, %1;" : "=f"(y) : "f"(x));
    return y;
}
__device__ __forceinline__ unsigned sptr(const void* p) {
    return (unsigned)__cvta_generic_to_shared(p);
}
__device__ __forceinline__ void ldsm4(unsigned r[4], unsigned a) {
    asm volatile("ldmatrix.sync.aligned.m8n8.x4.shared.b16 {%0,%1,%2,%3}, [%4];\n"
                 : "=r"(r[0]), "=r"(r[1]), "=r"(r[2]), "=r"(r[3]) : "r"(a));
}
__device__ __forceinline__ void ldsm2(unsigned& r0, unsigned& r1, unsigned a) {
    asm volatile("ldmatrix.sync.aligned.m8n8.x2.shared.b16 {%0,%1}, [%2];\n"
                 : "=r"(r0), "=r"(r1) : "r"(a));
}
__device__ __forceinline__ void ldsm2t(unsigned& r0, unsigned& r1, unsigned a) {
    asm volatile("ldmatrix.sync.aligned.m8n8.x2.trans.shared.b16 {%0,%1}, [%2];\n"
                 : "=r"(r0), "=r"(r1) : "r"(a));
}
__device__ __forceinline__ void cpasync16(unsigned saddr, const void* g) {
    asm volatile("cp.async.cg.shared.global [%0], [%1], 16;\n"
                 :: "r"(saddr), "l"(g));
}
__device__ __forceinline__ void cpcommit() {
    asm volatile("cp.async.commit_group;\n");
}
template <int N>
__device__ __forceinline__ void cpwaitg() {
    asm volatile("cp.async.wait_group %0;\n" :: "n"(N));
}

// ---------------------------------------------------------------------------
// fused fp32 -> bf16 conversions; contact is additionally scaled by 0.125
// (the 1/sqrt(D) part of the attention scale).
// ---------------------------------------------------------------------------
__global__ __launch_bounds__(256)
void cvt_all(const float* __restrict__ Ct, const float* __restrict__ X,
             const float* __restrict__ Wq, const float* __restrict__ Wk,
             const float* __restrict__ Wv, const float* __restrict__ Wo,
             bf16* dC, bf16* dX, bf16* dWq, bf16* dWk, bf16* dWv, bf16* dWo)
{
    int b = blockIdx.x;
    const float* s; bf16* d; size_t off; float mul = 1.f;
    if (b < 4096)      { s = Ct; d = dC;  off = b; mul = 0.125f; }
    else if (b < 5120) { s = X;  d = dX;  off = b - 4096; }
    else if (b < 5248) { s = Wq; d = dWq; off = b - 5120; }
    else if (b < 5376) { s = Wk; d = dWk; off = b - 5248; }
    else if (b < 5504) { s = Wv; d = dWv; off = b - 5376; }
    else               { s = Wo; d = dWo; off = b - 5504; }
    size_t base = off * 4096 + (size_t)threadIdx.x * 4;
#pragma unroll
    for (int r = 0; r < 4; r++) {
        float4 v = *(const float4*)&s[base + r * 1024];
        uint2 o;
        o.x = pack_bf16(v.x * mul, v.y * mul);
        o.y = pack_bf16(v.z * mul, v.w * mul);
        *(uint2*)&d[base + r * 1024] = o;
    }
}

// ---------------------------------------------------------------------------
// bf16 tensor-core GEMM, cp.async double-buffered.
// Output modes: Cf (fp32+resid)  >  C8 (e4m3, optional per-head Q scale)  >
// Cb (bf16).
// ---------------------------------------------------------------------------
__global__ __launch_bounds__(256, 2)
void gemm_bf16(const bf16* __restrict__ A, int lda,
               const bf16* __restrict__ B0, const bf16* __restrict__ B1,
               const bf16* __restrict__ B2, int ldb, int K,
               const float* __restrict__ bias0, const float* __restrict__ bias1,
               const float* __restrict__ bias2,
               const float* __restrict__ resid, int ldr,
               float* __restrict__ Cf,
               uint8_t* __restrict__ C8q, uint8_t* __restrict__ C8k,
               bf16* __restrict__ Cbv, int ldc,
               const float* __restrict__ wcq)
{
    const int z = blockIdx.z;
    const bf16* B = (z == 0) ? B0 : (z == 1) ? B1 : B2;
    const float* bias = (z == 0) ? bias0 : (z == 1) ? bias1 : bias2;
    uint8_t* C8 = (z == 0) ? C8q : (z == 1) ? C8k : nullptr;

    __shared__ bf16 As[2][128][40];
    __shared__ bf16 Bs[2][128][40];

    const int tid = threadIdx.x;
    const int lane = tid & 31, wid = tid >> 5;
    const int g = lane >> 2, t = lane & 3;
    const int wm = wid >> 2, wn = wid & 3;
    const int rm = wm * 64, rn = wn * 32;
    const int m0 = blockIdx.y * 128, n0 = blockIdx.x * 128;

    const int frow = tid >> 2, fcol = (tid & 3) * 8;
    const bf16* Ag0 = A + (size_t)(m0 + frow) * lda + fcol;
    const bf16* Ag1 = A + (size_t)(m0 + frow + 64) * lda + fcol;
    const bf16* Bg0 = B + (size_t)(n0 + frow) * ldb + fcol;
    const bf16* Bg1 = B + (size_t)(n0 + frow + 64) * ldb + fcol;

    float acc[4][4][4];
#pragma unroll
    for (int a = 0; a < 4; a++)
#pragma unroll
        for (int b = 0; b < 4; b++)
#pragma unroll
            for (int c = 0; c < 4; c++) acc[a][b][c] = 0.f;

    const int nk = K / 32;
    cpasync16(sptr(&As[0][frow][fcol]), Ag0);
    cpasync16(sptr(&As[0][frow + 64][fcol]), Ag1);
    cpasync16(sptr(&Bs[0][frow][fcol]), Bg0);
    cpasync16(sptr(&Bs[0][frow + 64][fcol]), Bg1);
    cpcommit();
    if (nk > 1) {
        cpasync16(sptr(&As[1][frow][fcol]), Ag0 + 32);
        cpasync16(sptr(&As[1][frow + 64][fcol]), Ag1 + 32);
        cpasync16(sptr(&Bs[1][frow][fcol]), Bg0 + 32);
        cpasync16(sptr(&Bs[1][frow + 64][fcol]), Bg1 + 32);
    }
    cpcommit();

    for (int kt = 0; kt < nk; kt++) {
        const int buf = kt & 1;
        if (kt + 1 < nk) cpwaitg<1>(); else cpwaitg<0>();
        __syncthreads();

        const unsigned Abase = sptr(&As[buf][0][0]) +
            ((rm + (lane & 15)) * 40 + (lane >> 4) * 8) * 2;
        const unsigned Bbase = sptr(&Bs[buf][0][0]) +
            ((rn + (lane & 7)) * 40 + ((lane >> 3) & 1) * 8) * 2;
#pragma unroll
        for (int ks = 0; ks < 2; ks++) {
            unsigned afr[4][4];
#pragma unroll
            for (int mf = 0; mf < 4; mf++)
                ldsm4(afr[mf], Abase + mf * 1280 + ks * 32);
#pragma unroll
            for (int nf = 0; nf < 4; nf++) {
                unsigned b0, b1;
                ldsm2(b0, b1, Bbase + nf * 640 + ks * 32);
#pragma unroll
                for (int mf = 0; mf < 4; mf++)
                    mma16816(acc[mf][nf], afr[mf], b0, b1);
            }
        }
        __syncthreads();
        if (kt + 2 < nk) {
            const int ko = (kt + 2) * 32;
            cpasync16(sptr(&As[buf][frow][fcol]), Ag0 + ko);
            cpasync16(sptr(&As[buf][frow + 64][fcol]), Ag1 + ko);
            cpasync16(sptr(&Bs[buf][frow][fcol]), Bg0 + ko);
            cpasync16(sptr(&Bs[buf][frow + 64][fcol]), Bg1 + ko);
        }
        cpcommit();
    }

#pragma unroll
    for (int mf = 0; mf < 4; mf++) {
        const int m = m0 + rm + mf * 16 + g;
#pragma unroll
        for (int nf = 0; nf < 4; nf++) {
            const int n = n0 + rn + nf * 8 + 2 * t;
            float2 bb = *(const float2*)&bias[n];
            float v0 = acc[mf][nf][0] + bb.x;
            float v1 = acc[mf][nf][1] + bb.y;
            float v2 = acc[mf][nf][2] + bb.x;
            float v3 = acc[mf][nf][3] + bb.y;
            if (Cf) {
                float2 r0 = *(const float2*)&resid[(size_t)m * ldr + n];
                float2 r1 = *(const float2*)&resid[(size_t)(m + 8) * ldr + n];
                *(float2*)&Cf[(size_t)m * ldc + n] = make_float2(v0 + r0.x, v1 + r0.y);
                *(float2*)&Cf[(size_t)(m + 8) * ldc + n] = make_float2(v2 + r1.x, v3 + r1.y);
            } else if (C8) {
                float sc = 1.f;
                if (z == 0) sc = 1.44269504f * wcq[n >> 6];  // Q: fold log2e*Wc
                *(unsigned short*)&C8[(size_t)m * ldc + n] =
                    pack_e4m3(v0 * sc, v1 * sc);
                *(unsigned short*)&C8[(size_t)(m + 8) * ldc + n] =
                    pack_e4m3(v2 * sc, v3 * sc);
            } else {
                *(unsigned*)&Cbv[(size_t)m * ldc + n] = pack_bf16(v0, v1);
                *(unsigned*)&Cbv[(size_t)(m + 8) * ldc + n] = pack_bf16(v2, v3);
            }
        }
    }
}

// ---------------------------------------------------------------------------
// Flash attention: QK^T in e4m3 (m16n8k32, 2x rate), PV in bf16.
// 128 q-rows/CTA, 4 warps x 32 rows (2 m-tiles), no-max softmax (score
// scale pre-folded: Q has log2e*Wc, contact has 0.125), chunked
// QK->exp->PV, contact/K/V staged via cp.async 2-stage rings.
// Smem bytes: Q8 10240 | K8 2x5120 | V 2x9216 | C 2x18432 = 75776
// grid = (NH, S/128), block = 128.
// ---------------------------------------------------------------------------
__global__ __launch_bounds__(128, 2)
void attn_mma(const uint8_t* __restrict__ Q8g, const uint8_t* __restrict__ K8g,
              const bf16* __restrict__ Vg, const bf16* __restrict__ contact,
              bf16* __restrict__ O)
{
    extern __shared__ char smc[];
    char* Qs = smc;                        // fp8 [128][80B]
    char* Ks = smc + 10240;                // fp8 [2][64][80B]
    bf16* Vs = (bf16*)(smc + 20480);       // bf16 [2][64][72]
    bf16* Cs = (bf16*)(smc + 38912);       // bf16 [2][128][72]

    const int tid = threadIdx.x;
    const int lane = tid & 31, wid = tid >> 5;
    const int g = lane >> 2, t = lane & 3;
    const int h = blockIdx.x;
    const int q0 = blockIdx.y * 128;
    const int wr0 = wid * 32;

    // fill mappings
    const int qrow = tid >> 2, qseg = (tid & 3) * 16;   // fp8: 16B segs
    const int vrow = tid >> 3, vseg = (tid & 7) * 8;    // bf16: 8-elem segs

    // ---- prologue: Q + K(0) + V(0) + C(0), one group ----
#pragma unroll
    for (int r = 0; r < 4; r++) {
        int row = qrow + 32 * r;
        cpasync16(sptr(Qs + row * 80 + qseg),
                  &Q8g[(size_t)(q0 + row) * NODE + h * HD + qseg]);
    }
#pragma unroll
    for (int r = 0; r < 2; r++) {
        int row = qrow + 32 * r;
        cpasync16(sptr(Ks + row * 80 + qseg),
                  &K8g[(size_t)row * NODE + h * HD + qseg]);
    }
#pragma unroll
    for (int r = 0; r < 4; r++) {
        int row = vrow + 16 * r;
        cpasync16(sptr(Vs + row * 72 + vseg),
                  &Vg[(size_t)row * NODE + h * HD + vseg]);
    }
#pragma unroll
    for (int r = 0; r < 8; r++) {
        int row = vrow + 16 * r;
        cpasync16(sptr(Cs + row * 72 + vseg),
                  &contact[(size_t)(q0 + row) * S_LEN + vseg]);
    }
    cpcommit();
    cpwaitg<0>();
    __syncthreads();

    // ---- hoist Q fragments (fp8, 2 k32 steps) ----
    unsigned qf[2][2][4];
#pragma unroll
    for (int mt = 0; mt < 2; mt++) {
        const unsigned qa = sptr(Qs) +
            (wr0 + mt * 16 + (lane & 15)) * 80 + (lane >> 4) * 16;
#pragma unroll
        for (int ks = 0; ks < 2; ks++)
            ldsm4(qf[mt][ks], qa + ks * 32);
    }

    float oc[2][8][4];
#pragma unroll
    for (int mt = 0; mt < 2; mt++)
#pragma unroll
        for (int nf = 0; nf < 8; nf++)
#pragma unroll
            for (int j = 0; j < 4; j++) oc[mt][nf][j] = 0.f;
    float lacc[2][2] = {{0.f, 0.f}, {0.f, 0.f}};

    for (int kb = 0; kb < NKB; kb++) {
        const int buf = kb & 1;
        if (kb > 0) {
            cpwaitg<0>();
            __syncthreads();
        }

        // distance-1 prefetch of K/V/C(kb+1)
        if (kb + 1 < NKB) {
            const int nb = buf ^ 1;
            const size_t gr = (size_t)(kb + 1) * 64;
            char* dK = Ks + nb * 5120;
            bf16* dV = Vs + nb * 4608;
            bf16* dC = Cs + nb * 9216;
#pragma unroll
            for (int r = 0; r < 2; r++) {
                int row = qrow + 32 * r;
                cpasync16(sptr(dK + row * 80 + qseg),
                          &K8g[(gr + row) * NODE + h * HD + qseg]);
            }
#pragma unroll
            for (int r = 0; r < 4; r++) {
                int row = vrow + 16 * r;
                cpasync16(sptr(dV + row * 72 + vseg),
                          &Vg[(gr + row) * NODE + h * HD + vseg]);
            }
#pragma unroll
            for (int r = 0; r < 8; r++) {
                int row = vrow + 16 * r;
                cpasync16(sptr(dC + row * 72 + vseg),
                          &contact[(size_t)(q0 + row) * S_LEN + gr + vseg]);
            }
        }
        cpcommit();

        const unsigned kAddr = sptr(Ks + buf * 5120) +
            (lane & 7) * 80 + ((lane >> 3) & 1) * 16;
        const unsigned vAddr = sptr(Vs + buf * 4608) + (lane & 15) * 144;
        const bf16* Cb = Cs + buf * 9216;

        // ---- 4 chunks of 16 keys: QK(fp8) -> exp -> PV(bf16) ----
#pragma unroll
        for (int ch = 0; ch < 4; ch++) {
            const int n0 = 2 * ch;
            // contact from smem (conflict-free LDS.32)
            unsigned cu[4][2];
#pragma unroll
            for (int i = 0; i < 4; i++) {
                const bf16* crp = Cb + (wr0 + g + 8 * i) * 72 + 2 * t;
#pragma unroll
                for (int j = 0; j < 2; j++)
                    cu[i][j] = *(const unsigned*)&crp[(n0 + j) * 8];
            }

            // QK for the 2 n-frags (2 k32 mma each)
            float s[2][2][4];
#pragma unroll
            for (int j = 0; j < 2; j++) {
                unsigned b0[2], b1[2];
#pragma unroll
                for (int ks = 0; ks < 2; ks++)
                    ldsm2(b0[ks], b1[ks],
                          kAddr + (n0 + j) * 640 + ks * 32);
#pragma unroll
                for (int q = 0; q < 4; q++) {
                    s[0][j][q] = 0.f;
                    s[1][j][q] = 0.f;
                }
#pragma unroll
                for (int ks = 0; ks < 2; ks++) {
                    mma16832f8(s[0][j], qf[0][ks], b0[ks], b1[ks]);
                    mma16832f8(s[1][j], qf[1][ks], b0[ks], b1[ks]);
                }
            }

            // exp + row sums + pack (A fragments for PV)
            unsigned apk[2][4];
#pragma unroll
            for (int mt = 0; mt < 2; mt++) {
#pragma unroll
                for (int j = 0; j < 2; j++) {
                    float2 cf0 = __bfloat1622float2(
                        *(const bf162*)&cu[2 * mt][j]);
                    float2 cf1 = __bfloat1622float2(
                        *(const bf162*)&cu[2 * mt + 1][j]);
                    float e0 = ex2(s[mt][j][0] * cf0.x);
                    float e1 = ex2(s[mt][j][1] * cf0.y);
                    float e2 = ex2(s[mt][j][2] * cf1.x);
                    float e3 = ex2(s[mt][j][3] * cf1.y);
                    lacc[mt][0] += e0 + e1;
                    lacc[mt][1] += e2 + e3;
                    apk[mt][2 * j] = pack_bf16(e0, e1);
                    apk[mt][2 * j + 1] = pack_bf16(e2, e3);
                }
            }

            // PV for this 16-key chunk (bf16)
#pragma unroll
            for (int nfd = 0; nfd < 8; nfd++) {
                unsigned b0, b1;
                ldsm2t(b0, b1, vAddr + ch * 2304 + nfd * 16);
                mma16816(oc[0][nfd], apk[0], b0, b1);
                mma16816(oc[1][nfd], apk[1], b0, b1);
            }
        }
    }

    // ---- normalize + store flat [H][S][D] bf16 ----
#pragma unroll
    for (int mt = 0; mt < 2; mt++) {
        float la = lacc[mt][0], lb = lacc[mt][1];
        la += __shfl_xor_sync(0xffffffffu, la, 1);
        la += __shfl_xor_sync(0xffffffffu, la, 2);
        lb += __shfl_xor_sync(0xffffffffu, lb, 1);
        lb += __shfl_xor_sync(0xffffffffu, lb, 2);
        const float inv0 = 1.f / la;
        const float inv1 = 1.f / lb;
        bf16* dst0 = O + (size_t)h * S_LEN * HD +
                     (size_t)(q0 + wr0 + mt * 16 + g) * HD;
        bf16* dst1 = dst0 + 8 * HD;
#pragma unroll
        for (int nf = 0; nf < 8; nf++) {
            int col = nf * 8 + 2 * t;
            *(unsigned*)&dst0[col] =
                pack_bf16(oc[mt][nf][0] * inv0, oc[mt][nf][1] * inv0);
            *(unsigned*)&dst1[col] =
                pack_bf16(oc[mt][nf][2] * inv1, oc[mt][nf][3] * inv1);
        }
    }
}

// ---------------------------------------------------------------------------
__global__ __launch_bounds__(256)
void ln_kernel(const float* __restrict__ x,
               const float* __restrict__ gamma,
               const float* __restrict__ beta,
               float* __restrict__ out)
{
    __shared__ float red[16];
    const int row = blockIdx.x;
    const int tid = threadIdx.x;
    const float* xr = x + (size_t)row * NODE;
    float2 v = *(const float2*)&xr[tid * 2];

    float ssum = v.x + v.y;
#pragma unroll
    for (int off = 16; off >= 1; off >>= 1)
        ssum += __shfl_xor_sync(0xffffffffu, ssum, off);
    if ((tid & 31) == 0) red[tid >> 5] = ssum;
    __syncthreads();
    float tot = 0.f;
#pragma unroll
    for (int w = 0; w < 8; w++) tot += red[w];
    const float mean = tot * (1.f / NODE);

    const float dx = v.x - mean, dy = v.y - mean;
    float sq = dx * dx + dy * dy;
#pragma unroll
    for (int off = 16; off >= 1; off >>= 1)
        sq += __shfl_xor_sync(0xffffffffu, sq, off);
    if ((tid & 31) == 0) red[8 + (tid >> 5)] = sq;
    __syncthreads();
    float tot2 = 0.f;
#pragma unroll
    for (int w = 0; w < 8; w++) tot2 += red[8 + w];
    const float inv = rsqrtf(tot2 * (1.f / NODE) + 1e-5f);

    const int n = tid * 2;
    float2 gm = *(const float2*)&gamma[n];
    float2 bt = *(const float2*)&beta[n];
    float2 o;
    o.x = dx * inv * gm.x + bt.x;
    o.y = dy * inv * gm.y + bt.y;
    *(float2*)&out[(size_t)row * NODE + n] = o;
}

// ---------------------------------------------------------------------------
extern "C" void kernel_launch(void* const* d_in, const int* in_sizes, int n_in,
                              void* d_out, int out_size)
{
    const float* X     = (const float*)d_in[0];
    const float* Ct    = (const float*)d_in[1];
    const float* Wq    = (const float*)d_in[2];
    const float* bq    = (const float*)d_in[3];
    const float* Wk    = (const float*)d_in[4];
    const float* bk    = (const float*)d_in[5];
    const float* Wv    = (const float*)d_in[6];
    const float* bv    = (const float*)d_in[7];
    const float* Wc    = (const float*)d_in[8];
    const float* Wo    = (const float*)d_in[9];
    const float* bo    = (const float*)d_in[10];
    const float* gamma = (const float*)d_in[11];
    const float* beta  = (const float*)d_in[12];
    float* out = (float*)d_out;

    void *pX, *pWq, *pWk, *pWv, *pWo, *pC, *pQ8, *pK8, *pV, *pO, *pAug;
    cudaGetSymbolAddress(&pX, g_Xbf);
    cudaGetSymbolAddress(&pWq, g_Wqb);
    cudaGetSymbolAddress(&pWk, g_Wkb);
    cudaGetSymbolAddress(&pWv, g_Wvb);
    cudaGetSymbolAddress(&pWo, g_Wob);
    cudaGetSymbolAddress(&pC, g_Cbf);
    cudaGetSymbolAddress(&pQ8, g_Q8);
    cudaGetSymbolAddress(&pK8, g_K8);
    cudaGetSymbolAddress(&pV, g_Vbf);
    cudaGetSymbolAddress(&pO, g_Obf);
    cudaGetSymbolAddress(&pAug, g_aug);
    bf16* Xbf = (bf16*)pX;
    bf16* Wqb = (bf16*)pWq;
    bf16* Wkb = (bf16*)pWk;
    bf16* Wvb = (bf16*)pWv;
    bf16* Wob = (bf16*)pWo;
    bf16* Cbf = (bf16*)pC;
    uint8_t* Q8 = (uint8_t*)pQ8;
    uint8_t* K8 = (uint8_t*)pK8;
    bf16* Vbf = (bf16*)pV;
    bf16* Obf = (bf16*)pO;
    float* aug = (float*)pAug;

    // 1. fp32 -> bf16 (contact*0.125, X, weights)
    cvt_all<<<5568, 256>>>(Ct, X, Wq, Wk, Wv, Wo,
                           Cbf, Xbf, Wqb, Wkb, Wvb, Wob);

    // 2. fused QKV projection: Q -> e4m3 (scaled), K -> e4m3, V -> bf16
    gemm_bf16<<<dim3(NODE / 128, S_LEN / 128, 3), 256>>>(
        Xbf, IN_DIM, Wqb, Wkb, Wvb, IN_DIM, IN_DIM,
        bq, bk, bv, nullptr, 0, nullptr,
        Q8, K8, Vbf, NODE, Wc);

    // 3. flash attention (fp8 QK, bf16 PV)
    const int smem_bytes = 75776;
    cudaFuncSetAttribute(attn_mma,
                         cudaFuncAttributeMaxDynamicSharedMemorySize,
                         smem_bytes);
    attn_mma<<<dim3(NH, S_LEN / 128), 128, smem_bytes>>>(Q8, K8, Vbf, Cbf, Obf);

    // 4. output projection + bias + residual (bf16 in, fp32 out)
    gemm_bf16<<<dim3(NODE / 128, S_LEN / 128, 1), 256>>>(
        Obf, NODE, Wob, Wob, Wob, NODE, NODE,
        bo, bo, bo, X, IN_DIM, aug,
        nullptr, nullptr, nullptr, NODE, nullptr);

    // 5. LayerNorm
    ln_kernel<<<S_LEN, 256>>>(aug, gamma, beta, out);
}

// round 13
// speedup vs baseline: 1.1055x; 1.1055x over previous
#include <cuda_runtime.h>
#include <cuda_bf16.h>
#include <math.h>
#include <stdint.h>

#define S_LEN 4096
#define IN_DIM 1024
#define NODE 512
#define NH 8
#define HD 64
#define NKB (S_LEN / 64)

typedef __nv_bfloat16 bf16;
typedef __nv_bfloat162 bf162;

// ---------------- device scratch ----------------
__device__ bf16  g_Xbf[S_LEN * IN_DIM];
__device__ bf16  g_Wqb[NODE * IN_DIM];
__device__ bf16  g_Wkb[NODE * IN_DIM];
__device__ bf16  g_Wvb[NODE * IN_DIM];
__device__ bf16  g_Wob[NODE * NODE];
__device__ bf16  g_Cbf[(size_t)S_LEN * S_LEN];   // contact bf16 (32 MB)
__device__ bf16  g_QKVb[3 * S_LEN * NODE];
__device__ bf16  g_Obf[NH * S_LEN * HD];
__device__ float g_aug[S_LEN * NODE];

// ---------------- helpers ----------------
__device__ __forceinline__ void mma16816(float c[4], const unsigned a[4],
                                         unsigned b0, unsigned b1) {
    asm volatile(
        "mma.sync.aligned.m16n8k16.row.col.f32.bf16.bf16.f32 "
        "{%0,%1,%2,%3}, {%4,%5,%6,%7}, {%8,%9}, {%0,%1,%2,%3};\n"
        : "+f"(c[0]), "+f"(c[1]), "+f"(c[2]), "+f"(c[3])
        : "r"(a[0]), "r"(a[1]), "r"(a[2]), "r"(a[3]), "r"(b0), "r"(b1));
}
__device__ __forceinline__ unsigned pack_bf16(float x, float y) {
    unsigned r;
    asm("cvt.rn.bf16x2.f32 %0, %1, %2;" : "=r"(r) : "f"(y), "f"(x));
    return r;
}
__device__ __forceinline__ float ex2(float x) {
    float y;
    asm("ex2.approx.f32 %0, %1;" : "=f"(y) : "f"(x));
    return y;
}
__device__ __forceinline__ unsigned sptr(const void* p) {
    return (unsigned)__cvta_generic_to_shared(p);
}
__device__ __forceinline__ void ldsm4(unsigned r[4], unsigned a) {
    asm volatile("ldmatrix.sync.aligned.m8n8.x4.shared.b16 {%0,%1,%2,%3}, [%4];\n"
                 : "=r"(r[0]), "=r"(r[1]), "=r"(r[2]), "=r"(r[3]) : "r"(a));
}
__device__ __forceinline__ void ldsm2(unsigned& r0, unsigned& r1, unsigned a) {
    asm volatile("ldmatrix.sync.aligned.m8n8.x2.shared.b16 {%0,%1}, [%2];\n"
                 : "=r"(r0), "=r"(r1) : "r"(a));
}
__device__ __forceinline__ void ldsm4t(unsigned r[4], unsigned a) {
    asm volatile("ldmatrix.sync.aligned.m8n8.x4.trans.shared.b16 {%0,%1,%2,%3}, [%4];\n"
                 : "=r"(r[0]), "=r"(r[1]), "=r"(r[2]), "=r"(r[3]) : "r"(a));
}
__device__ __forceinline__ void cpasync16(unsigned saddr, const void* g) {
    asm volatile("cp.async.cg.shared.global [%0], [%1], 16;\n"
                 :: "r"(saddr), "l"(g));
}
__device__ __forceinline__ void cpcommit() {
    asm volatile("cp.async.commit_group;\n");
}
template <int N>
__device__ __forceinline__ void cpwaitg() {
    asm volatile("cp.async.wait_group %0;\n" :: "n"(N));
}

// ---------------------------------------------------------------------------
// fused fp32 -> bf16 conversions, 4 independent float4 chains per thread.
// ---------------------------------------------------------------------------
__global__ __launch_bounds__(256)
void cvt_all(const float* __restrict__ Ct, const float* __restrict__ X,
             const float* __restrict__ Wq, const float* __restrict__ Wk,
             const float* __restrict__ Wv, const float* __restrict__ Wo,
             bf16* dC, bf16* dX, bf16* dWq, bf16* dWk, bf16* dWv, bf16* dWo)
{
    int b = blockIdx.x;
    const float* s; bf16* d; size_t off;
    if (b < 4096)      { s = Ct; d = dC;  off = b; }
    else if (b < 5120) { s = X;  d = dX;  off = b - 4096; }
    else if (b < 5248) { s = Wq; d = dWq; off = b - 5120; }
    else if (b < 5376) { s = Wk; d = dWk; off = b - 5248; }
    else if (b < 5504) { s = Wv; d = dWv; off = b - 5376; }
    else               { s = Wo; d = dWo; off = b - 5504; }
    size_t base = off * 4096 + (size_t)threadIdx.x * 4;
#pragma unroll
    for (int r = 0; r < 4; r++) {
        float4 v = *(const float4*)&s[base + r * 1024];
        uint2 o;
        o.x = pack_bf16(v.x, v.y);
        o.y = pack_bf16(v.z, v.w);
        *(uint2*)&d[base + r * 1024] = o;
    }
}

// ---------------------------------------------------------------------------
// bf16 tensor-core GEMM, cp.async double-buffered (R11, unchanged).
// wcq != null: z==0 output (Q) scaled by 0.18033688*wcq[n/64].
// ---------------------------------------------------------------------------
__global__ __launch_bounds__(256, 2)
void gemm_bf16(const bf16* __restrict__ A, int lda,
               const bf16* __restrict__ B0, const bf16* __restrict__ B1,
               const bf16* __restrict__ B2, int ldb, int K,
               const float* __restrict__ bias0, const float* __restrict__ bias1,
               const float* __restrict__ bias2,
               const float* __restrict__ resid, int ldr,
               float* __restrict__ Cf,
               bf16* __restrict__ Cb0, bf16* __restrict__ Cb1,
               bf16* __restrict__ Cb2, int ldc,
               const float* __restrict__ wcq)
{
    const int z = blockIdx.z;
    const bf16* B = (z == 0) ? B0 : (z == 1) ? B1 : B2;
    const float* bias = (z == 0) ? bias0 : (z == 1) ? bias1 : bias2;
    bf16* Cb = (z == 0) ? Cb0 : (z == 1) ? Cb1 : Cb2;
    const bool doScale = (wcq != nullptr) && (z == 0);

    __shared__ bf16 As[2][128][40];
    __shared__ bf16 Bs[2][128][40];

    const int tid = threadIdx.x;
    const int lane = tid & 31, wid = tid >> 5;
    const int g = lane >> 2, t = lane & 3;
    const int wm = wid >> 2, wn = wid & 3;
    const int rm = wm * 64, rn = wn * 32;
    const int m0 = blockIdx.y * 128, n0 = blockIdx.x * 128;

    const int frow = tid >> 2, fcol = (tid & 3) * 8;
    const bf16* Ag0 = A + (size_t)(m0 + frow) * lda + fcol;
    const bf16* Ag1 = A + (size_t)(m0 + frow + 64) * lda + fcol;
    const bf16* Bg0 = B + (size_t)(n0 + frow) * ldb + fcol;
    const bf16* Bg1 = B + (size_t)(n0 + frow + 64) * ldb + fcol;

    float acc[4][4][4];
#pragma unroll
    for (int a = 0; a < 4; a++)
#pragma unroll
        for (int b = 0; b < 4; b++)
#pragma unroll
            for (int c = 0; c < 4; c++) acc[a][b][c] = 0.f;

    const int nk = K / 32;
    cpasync16(sptr(&As[0][frow][fcol]), Ag0);
    cpasync16(sptr(&As[0][frow + 64][fcol]), Ag1);
    cpasync16(sptr(&Bs[0][frow][fcol]), Bg0);
    cpasync16(sptr(&Bs[0][frow + 64][fcol]), Bg1);
    cpcommit();
    if (nk > 1) {
        cpasync16(sptr(&As[1][frow][fcol]), Ag0 + 32);
        cpasync16(sptr(&As[1][frow + 64][fcol]), Ag1 + 32);
        cpasync16(sptr(&Bs[1][frow][fcol]), Bg0 + 32);
        cpasync16(sptr(&Bs[1][frow + 64][fcol]), Bg1 + 32);
    }
    cpcommit();

    for (int kt = 0; kt < nk; kt++) {
        const int buf = kt & 1;
        if (kt + 1 < nk) cpwaitg<1>(); else cpwaitg<0>();
        __syncthreads();

        const unsigned Abase = sptr(&As[buf][0][0]) +
            ((rm + (lane & 15)) * 40 + (lane >> 4) * 8) * 2;
        const unsigned Bbase = sptr(&Bs[buf][0][0]) +
            ((rn + (lane & 7)) * 40 + ((lane >> 3) & 1) * 8) * 2;
#pragma unroll
        for (int ks = 0; ks < 2; ks++) {
            unsigned afr[4][4];
#pragma unroll
            for (int mf = 0; mf < 4; mf++)
                ldsm4(afr[mf], Abase + mf * 1280 + ks * 32);
#pragma unroll
            for (int nf = 0; nf < 4; nf++) {
                unsigned b0, b1;
                ldsm2(b0, b1, Bbase + nf * 640 + ks * 32);
#pragma unroll
                for (int mf = 0; mf < 4; mf++)
                    mma16816(acc[mf][nf], afr[mf], b0, b1);
            }
        }
        __syncthreads();
        if (kt + 2 < nk) {
            const int ko = (kt + 2) * 32;
            cpasync16(sptr(&As[buf][frow][fcol]), Ag0 + ko);
            cpasync16(sptr(&As[buf][frow + 64][fcol]), Ag1 + ko);
            cpasync16(sptr(&Bs[buf][frow][fcol]), Bg0 + ko);
            cpasync16(sptr(&Bs[buf][frow + 64][fcol]), Bg1 + ko);
        }
        cpcommit();
    }

#pragma unroll
    for (int mf = 0; mf < 4; mf++) {
        const int m = m0 + rm + mf * 16 + g;
#pragma unroll
        for (int nf = 0; nf < 4; nf++) {
            const int n = n0 + rn + nf * 8 + 2 * t;
            float2 bb = *(const float2*)&bias[n];
            float v0 = acc[mf][nf][0] + bb.x;
            float v1 = acc[mf][nf][1] + bb.y;
            float v2 = acc[mf][nf][2] + bb.x;
            float v3 = acc[mf][nf][3] + bb.y;
            if (doScale) {
                const float sc = 0.18033688f * wcq[(n & (NODE - 1)) >> 6];
                v0 *= sc; v1 *= sc; v2 *= sc; v3 *= sc;
            }
            if (Cf) {
                float2 r0 = *(const float2*)&resid[(size_t)m * ldr + n];
                float2 r1 = *(const float2*)&resid[(size_t)(m + 8) * ldr + n];
                *(float2*)&Cf[(size_t)m * ldc + n] = make_float2(v0 + r0.x, v1 + r0.y);
                *(float2*)&Cf[(size_t)(m + 8) * ldc + n] = make_float2(v2 + r1.x, v3 + r1.y);
            } else {
                *(unsigned*)&Cb[(size_t)m * ldc + n] = pack_bf16(v0, v1);
                *(unsigned*)&Cb[(size_t)(m + 8) * ldc + n] = pack_bf16(v2, v3);
            }
        }
    }
}

// ---------------------------------------------------------------------------
// Flash attention (R11 structure + x4 ldsm batching): 128 q-rows/CTA,
// 4 warps x 32 rows, no-max softmax (scale pre-folded into Q), chunked
// QK->exp->PV, contact/K/V staged via cp.async 2-stage rings.
// grid = (NH, S/128), block = 128.
// ---------------------------------------------------------------------------
__global__ __launch_bounds__(128, 2)
void attn_mma(const bf16* __restrict__ qkv,
              const bf16* __restrict__ contact,
              bf16* __restrict__ O)
{
    extern __shared__ bf16 sm[];
    bf16* Qs = sm;                       // [128][72]
    bf16* KVs = sm + 9216;               // [2 stage][K|V][64*72]
    bf16* Cs = sm + 9216 + 18432;        // [2 stage][128][72]

    const int tid = threadIdx.x;
    const int lane = tid & 31, wid = tid >> 5;
    const int g = lane >> 2, t = lane & 3;
    const int h = blockIdx.x;
    const int q0 = blockIdx.y * 128;
    const int wr0 = wid * 32;

    const bf16* Qp = qkv;
    const bf16* Kp = qkv + (size_t)S_LEN * NODE;
    const bf16* Vp = qkv + 2 * (size_t)S_LEN * NODE;

    const int frow = tid >> 3, fcol = (tid & 7) * 8;

    // ---- prologue: Q + C(0) + KV(0), one group ----
#pragma unroll
    for (int r = 0; r < 8; r++) {
        int row = frow + 16 * r;
        cpasync16(sptr(&Qs[row * 72 + fcol]),
                  &Qp[(size_t)(q0 + row) * NODE + h * HD + fcol]);
        cpasync16(sptr(&Cs[row * 72 + fcol]),
                  &contact[(size_t)(q0 + row) * S_LEN + fcol]);
    }
#pragma unroll
    for (int r = 0; r < 4; r++) {
        int row = frow + 16 * r;
        cpasync16(sptr(&KVs[row * 72 + fcol]),
                  &Kp[(size_t)row * NODE + h * HD + fcol]);
        cpasync16(sptr(&KVs[4608 + row * 72 + fcol]),
                  &Vp[(size_t)row * NODE + h * HD + fcol]);
    }
    cpcommit();
    cpwaitg<0>();
    __syncthreads();

    // ---- hoist Q fragments ----
    unsigned qf[2][4][4];
#pragma unroll
    for (int mt = 0; mt < 2; mt++) {
        const unsigned qa = sptr(Qs) +
            ((wr0 + mt * 16 + (lane & 15)) * 72 + (lane >> 4) * 8) * 2;
#pragma unroll
        for (int ks = 0; ks < 4; ks++)
            ldsm4(qf[mt][ks], qa + ks * 32);
    }

    float oc[2][8][4];
#pragma unroll
    for (int mt = 0; mt < 2; mt++)
#pragma unroll
        for (int nf = 0; nf < 8; nf++)
#pragma unroll
            for (int j = 0; j < 4; j++) oc[mt][nf][j] = 0.f;
    float lacc[2][2] = {{0.f, 0.f}, {0.f, 0.f}};

    for (int kb = 0; kb < NKB; kb++) {
        const int buf = kb & 1;
        if (kb > 0) {
            cpwaitg<0>();
            __syncthreads();
        }

        // distance-1 prefetch: C(kb+1) + KV(kb+1) into the other stage
        if (kb + 1 < NKB) {
            const int nb = buf ^ 1;
            const size_t gr = (size_t)(kb + 1) * 64;
            bf16* dK = KVs + nb * 9216;
            bf16* dC = Cs + nb * 9216;
#pragma unroll
            for (int r = 0; r < 8; r++) {
                int row = frow + 16 * r;
                cpasync16(sptr(&dC[row * 72 + fcol]),
                          &contact[(size_t)(q0 + row) * S_LEN + gr + fcol]);
            }
#pragma unroll
            for (int r = 0; r < 4; r++) {
                int row = frow + 16 * r;
                cpasync16(sptr(&dK[row * 72 + fcol]),
                          &Kp[(gr + row) * NODE + h * HD + fcol]);
                cpasync16(sptr(&dK[4608 + row * 72 + fcol]),
                          &Vp[(gr + row) * NODE + h * HD + fcol]);
            }
        }
        cpcommit();

        const bf16* Kb = KVs + buf * 9216;
        // x4 K loads: lanes 0..31 -> 4 matrices = b0/b1 of two k16 steps
        const unsigned kAddr4 = sptr(Kb) +
            ((lane & 7) * 72) * 2 + (lane >> 3) * 16;
        // x4 trans V loads: lanes 16..31 at +16B -> second d-frag
        const unsigned vAddr4 = sptr(Kb + 4608) +
            ((lane & 15) * 72) * 2 + (lane >> 4) * 16;
        const bf16* Cb = Cs + buf * 9216;

        // ---- 4 chunks of 16 keys: QK -> exp -> PV ----
#pragma unroll
        for (int ch = 0; ch < 4; ch++) {
            const int n0 = 2 * ch;
            // contact from smem (conflict-free LDS.32)
            unsigned cu[4][2];
#pragma unroll
            for (int i = 0; i < 4; i++) {
                const bf16* crp = Cb + (wr0 + g + 8 * i) * 72 + 2 * t;
#pragma unroll
                for (int j = 0; j < 2; j++)
                    cu[i][j] = *(const unsigned*)&crp[(n0 + j) * 8];
            }

            // QK for the 2 n-frags (2 x ldsm4 each: k0-31, k32-63)
            float s[2][2][4];
#pragma unroll
            for (int j = 0; j < 2; j++) {
                unsigned kf[8];
                ldsm4(kf, kAddr4 + (n0 + j) * 1152);
                ldsm4(kf + 4, kAddr4 + (n0 + j) * 1152 + 64);
#pragma unroll
                for (int q = 0; q < 4; q++) {
                    s[0][j][q] = 0.f;
                    s[1][j][q] = 0.f;
                }
#pragma unroll
                for (int ks = 0; ks < 4; ks++) {
                    mma16816(s[0][j], qf[0][ks], kf[2 * ks], kf[2 * ks + 1]);
                    mma16816(s[1][j], qf[1][ks], kf[2 * ks], kf[2 * ks + 1]);
                }
            }

            // exp + row sums + pack (A fragments for PV); scale pre-folded
            unsigned apk[2][4];
#pragma unroll
            for (int mt = 0; mt < 2; mt++) {
#pragma unroll
                for (int j = 0; j < 2; j++) {
                    float2 cf0 = __bfloat1622float2(
                        *(const bf162*)&cu[2 * mt][j]);
                    float2 cf1 = __bfloat1622float2(
                        *(const bf162*)&cu[2 * mt + 1][j]);
                    float e0 = ex2(s[mt][j][0] * cf0.x);
                    float e1 = ex2(s[mt][j][1] * cf0.y);
                    float e2 = ex2(s[mt][j][2] * cf1.x);
                    float e3 = ex2(s[mt][j][3] * cf1.y);
                    lacc[mt][0] += e0 + e1;
                    lacc[mt][1] += e2 + e3;
                    apk[mt][2 * j] = pack_bf16(e0, e1);
                    apk[mt][2 * j + 1] = pack_bf16(e2, e3);
                }
            }

            // PV for this 16-key chunk (x4 trans: 2 d-frags per ldsm)
#pragma unroll
            for (int nfp = 0; nfp < 4; nfp++) {
                unsigned vf[4];
                ldsm4t(vf, vAddr4 + ch * 2304 + nfp * 32);
                mma16816(oc[0][2 * nfp], apk[0], vf[0], vf[1]);
                mma16816(oc[1][2 * nfp], apk[1], vf[0], vf[1]);
                mma16816(oc[0][2 * nfp + 1], apk[0], vf[2], vf[3]);
                mma16816(oc[1][2 * nfp + 1], apk[1], vf[2], vf[3]);
            }
        }
    }

    // ---- normalize + store flat [H][S][D] bf16 ----
#pragma unroll
    for (int mt = 0; mt < 2; mt++) {
        float la = lacc[mt][0], lb = lacc[mt][1];
        la += __shfl_xor_sync(0xffffffffu, la, 1);
        la += __shfl_xor_sync(0xffffffffu, la, 2);
        lb += __shfl_xor_sync(0xffffffffu, lb, 1);
        lb += __shfl_xor_sync(0xffffffffu, lb, 2);
        const float inv0 = 1.f / la;
        const float inv1 = 1.f / lb;
        bf16* dst0 = O + (size_t)h * S_LEN * HD +
                     (size_t)(q0 + wr0 + mt * 16 + g) * HD;
        bf16* dst1 = dst0 + 8 * HD;
#pragma unroll
        for (int nf = 0; nf < 8; nf++) {
            int col = nf * 8 + 2 * t;
            *(unsigned*)&dst0[col] =
                pack_bf16(oc[mt][nf][0] * inv0, oc[mt][nf][1] * inv0);
            *(unsigned*)&dst1[col] =
                pack_bf16(oc[mt][nf][2] * inv1, oc[mt][nf][3] * inv1);
        }
    }
}

// ---------------------------------------------------------------------------
__global__ __launch_bounds__(256)
void ln_kernel(const float* __restrict__ x,
               const float* __restrict__ gamma,
               const float* __restrict__ beta,
               float* __restrict__ out)
{
    __shared__ float red[16];
    const int row = blockIdx.x;
    const int tid = threadIdx.x;
    const float* xr = x + (size_t)row * NODE;
    float2 v = *(const float2*)&xr[tid * 2];

    float ssum = v.x + v.y;
#pragma unroll
    for (int off = 16; off >= 1; off >>= 1)
        ssum += __shfl_xor_sync(0xffffffffu, ssum, off);
    if ((tid & 31) == 0) red[tid >> 5] = ssum;
    __syncthreads();
    float tot = 0.f;
#pragma unroll
    for (int w = 0; w < 8; w++) tot += red[w];
    const float mean = tot * (1.f / NODE);

    const float dx = v.x - mean, dy = v.y - mean;
    float sq = dx * dx + dy * dy;
#pragma unroll
    for (int off = 16; off >= 1; off >>= 1)
        sq += __shfl_xor_sync(0xffffffffu, sq, off);
    if ((tid & 31) == 0) red[8 + (tid >> 5)] = sq;
    __syncthreads();
    float tot2 = 0.f;
#pragma unroll
    for (int w = 0; w < 8; w++) tot2 += red[8 + w];
    const float inv = rsqrtf(tot2 * (1.f / NODE) + 1e-5f);

    const int n = tid * 2;
    float2 gm = *(const float2*)&gamma[n];
    float2 bt = *(const float2*)&beta[n];
    float2 o;
    o.x = dx * inv * gm.x + bt.x;
    o.y = dy * inv * gm.y + bt.y;
    *(float2*)&out[(size_t)row * NODE + n] = o;
}

// ---------------------------------------------------------------------------
extern "C" void kernel_launch(void* const* d_in, const int* in_sizes, int n_in,
                              void* d_out, int out_size)
{
    const float* X     = (const float*)d_in[0];
    const float* Ct    = (const float*)d_in[1];
    const float* Wq    = (const float*)d_in[2];
    const float* bq    = (const float*)d_in[3];
    const float* Wk    = (const float*)d_in[4];
    const float* bk    = (const float*)d_in[5];
    const float* Wv    = (const float*)d_in[6];
    const float* bv    = (const float*)d_in[7];
    const float* Wc    = (const float*)d_in[8];
    const float* Wo    = (const float*)d_in[9];
    const float* bo    = (const float*)d_in[10];
    const float* gamma = (const float*)d_in[11];
    const float* beta  = (const float*)d_in[12];
    float* out = (float*)d_out;

    void *pX, *pWq, *pWk, *pWv, *pWo, *pC, *pQKV, *pO, *pAug;
    cudaGetSymbolAddress(&pX, g_Xbf);
    cudaGetSymbolAddress(&pWq, g_Wqb);
    cudaGetSymbolAddress(&pWk, g_Wkb);
    cudaGetSymbolAddress(&pWv, g_Wvb);
    cudaGetSymbolAddress(&pWo, g_Wob);
    cudaGetSymbolAddress(&pC, g_Cbf);
    cudaGetSymbolAddress(&pQKV, g_QKVb);
    cudaGetSymbolAddress(&pO, g_Obf);
    cudaGetSymbolAddress(&pAug, g_aug);
    bf16* Xbf = (bf16*)pX;
    bf16* Wqb = (bf16*)pWq;
    bf16* Wkb = (bf16*)pWk;
    bf16* Wvb = (bf16*)pWv;
    bf16* Wob = (bf16*)pWo;
    bf16* Cbf = (bf16*)pC;
    bf16* qkv = (bf16*)pQKV;
    bf16* Obf = (bf16*)pO;
    float* aug = (float*)pAug;

    // 1. fp32 -> bf16 (contact, X, weights), 4-way ILP
    cvt_all<<<5568, 256>>>(Ct, X, Wq, Wk, Wv, Wo,
                           Cbf, Xbf, Wqb, Wkb, Wvb, Wob);

    // 2. fused QKV projection (Q scaled by per-head attn scale)
    gemm_bf16<<<dim3(NODE / 128, S_LEN / 128, 3), 256>>>(
        Xbf, IN_DIM, Wqb, Wkb, Wvb, IN_DIM, IN_DIM,
        bq, bk, bv, nullptr, 0, nullptr,
        qkv, qkv + (size_t)S_LEN * NODE, qkv + 2 * (size_t)S_LEN * NODE, NODE,
        Wc);

    // 3. flash attention (R11 + x4 ldsm batching)
    const int smem_bytes = (9216 + 18432 + 18432) * (int)sizeof(bf16); // 92160
    cudaFuncSetAttribute(attn_mma,
                         cudaFuncAttributeMaxDynamicSharedMemorySize,
                         smem_bytes);
    attn_mma<<<dim3(NH, S_LEN / 128), 128, smem_bytes>>>(qkv, Cbf, Obf);

    // 4. output projection + bias + residual
    gemm_bf16<<<dim3(NODE / 128, S_LEN / 128, 1), 256>>>(
        Obf, NODE, Wob, Wob, Wob, NODE, NODE,
        bo, bo, bo, X, IN_DIM, aug,
        nullptr, nullptr, nullptr, NODE, nullptr);

    // 5. LayerNorm
    ln_kernel<<<S_LEN, 256>>>(aug, gamma, beta, out);
}

// round 15
// speedup vs baseline: 1.1079x; 1.0021x over previous
#include <cuda_runtime.h>
#include <cuda_bf16.h>
#include <math.h>
#include <stdint.h>

#define S_LEN 4096
#define IN_DIM 1024
#define NODE 512
#define NH 8
#define HD 64
#define NKB (S_LEN / 64)

typedef __nv_bfloat16 bf16;
typedef __nv_bfloat162 bf162;

// ---------------- device scratch ----------------
__device__ bf16  g_Xbf[S_LEN * IN_DIM];
__device__ bf16  g_Wqb[NODE * IN_DIM];
__device__ bf16  g_Wkb[NODE * IN_DIM];
__device__ bf16  g_Wvb[NODE * IN_DIM];
__device__ bf16  g_Wob[NODE * NODE];
__device__ bf16  g_Cbf[(size_t)S_LEN * S_LEN];   // contact bf16 (32 MB)
__device__ bf16  g_QKVb[3 * S_LEN * NODE];
__device__ bf16  g_Obf[NH * S_LEN * HD];
__device__ float g_aug[S_LEN * NODE];

// ---------------- helpers ----------------
__device__ __forceinline__ void mma16816(float c[4], const unsigned a[4],
                                         unsigned b0, unsigned b1) {
    asm volatile(
        "mma.sync.aligned.m16n8k16.row.col.f32.bf16.bf16.f32 "
        "{%0,%1,%2,%3}, {%4,%5,%6,%7}, {%8,%9}, {%0,%1,%2,%3};\n"
        : "+f"(c[0]), "+f"(c[1]), "+f"(c[2]), "+f"(c[3])
        : "r"(a[0]), "r"(a[1]), "r"(a[2]), "r"(a[3]), "r"(b0), "r"(b1));
}
__device__ __forceinline__ unsigned pack_bf16(float x, float y) {
    unsigned r;
    asm("cvt.rn.bf16x2.f32 %0, %1, %2;" : "=r"(r) : "f"(y), "f"(x));
    return r;
}
__device__ __forceinline__ float ex2(float x) {
    float y;
    asm("ex2.approx.f32 %0, %1;" : "=f"(y) : "f"(x));
    return y;
}
__device__ __forceinline__ unsigned sptr(const void* p) {
    return (unsigned)__cvta_generic_to_shared(p);
}
__device__ __forceinline__ void ldsm4(unsigned r[4], unsigned a) {
    asm volatile("ldmatrix.sync.aligned.m8n8.x4.shared.b16 {%0,%1,%2,%3}, [%4];\n"
                 : "=r"(r[0]), "=r"(r[1]), "=r"(r[2]), "=r"(r[3]) : "r"(a));
}
__device__ __forceinline__ void ldsm4t(unsigned r[4], unsigned a) {
    asm volatile("ldmatrix.sync.aligned.m8n8.x4.trans.shared.b16 {%0,%1,%2,%3}, [%4];\n"
                 : "=r"(r[0]), "=r"(r[1]), "=r"(r[2]), "=r"(r[3]) : "r"(a));
}
__device__ __forceinline__ void cpasync16(unsigned saddr, const void* g) {
    asm volatile("cp.async.cg.shared.global [%0], [%1], 16;\n"
                 :: "r"(saddr), "l"(g));
}
__device__ __forceinline__ void cpcommit() {
    asm volatile("cp.async.commit_group;\n");
}
template <int N>
__device__ __forceinline__ void cpwaitg() {
    asm volatile("cp.async.wait_group %0;\n" :: "n"(N));
}

// ---------------------------------------------------------------------------
// fused fp32 -> bf16 conversions, 4 independent float4 chains per thread.
// ---------------------------------------------------------------------------
__global__ __launch_bounds__(256)
void cvt_all(const float* __restrict__ Ct, const float* __restrict__ X,
             const float* __restrict__ Wq, const float* __restrict__ Wk,
             const float* __restrict__ Wv, const float* __restrict__ Wo,
             bf16* dC, bf16* dX, bf16* dWq, bf16* dWk, bf16* dWv, bf16* dWo)
{
    int b = blockIdx.x;
    const float* s; bf16* d; size_t off;
    if (b < 4096)      { s = Ct; d = dC;  off = b; }
    else if (b < 5120) { s = X;  d = dX;  off = b - 4096; }
    else if (b < 5248) { s = Wq; d = dWq; off = b - 5120; }
    else if (b < 5376) { s = Wk; d = dWk; off = b - 5248; }
    else if (b < 5504) { s = Wv; d = dWv; off = b - 5376; }
    else               { s = Wo; d = dWo; off = b - 5504; }
    size_t base = off * 4096 + (size_t)threadIdx.x * 4;
#pragma unroll
    for (int r = 0; r < 4; r++) {
        float4 v = *(const float4*)&s[base + r * 1024];
        uint2 o;
        o.x = pack_bf16(v.x, v.y);
        o.y = pack_bf16(v.z, v.w);
        *(uint2*)&d[base + r * 1024] = o;
    }
}

// ---------------------------------------------------------------------------
// bf16 tensor-core GEMM, BK=64, cp.async double-buffered, x4 ldsm batching.
// Dynamic smem: As [2][128][72] | Bs [2][128][72] bf16 = 73728 B.
// wcq != null: z==0 output (Q) scaled by 0.18033688*wcq[n/64].
// ---------------------------------------------------------------------------
__global__ __launch_bounds__(256, 2)
void gemm_bf16(const bf16* __restrict__ A, int lda,
               const bf16* __restrict__ B0, const bf16* __restrict__ B1,
               const bf16* __restrict__ B2, int ldb, int K,
               const float* __restrict__ bias0, const float* __restrict__ bias1,
               const float* __restrict__ bias2,
               const float* __restrict__ resid, int ldr,
               float* __restrict__ Cf,
               bf16* __restrict__ Cb0, bf16* __restrict__ Cb1,
               bf16* __restrict__ Cb2, int ldc,
               const float* __restrict__ wcq)
{
    const int z = blockIdx.z;
    const bf16* B = (z == 0) ? B0 : (z == 1) ? B1 : B2;
    const float* bias = (z == 0) ? bias0 : (z == 1) ? bias1 : bias2;
    bf16* Cb = (z == 0) ? Cb0 : (z == 1) ? Cb1 : Cb2;
    const bool doScale = (wcq != nullptr) && (z == 0);

    extern __shared__ bf16 gsm[];
    bf16* As = gsm;                 // [2][128*72]
    bf16* Bs = gsm + 2 * 9216;      // [2][128*72]

    const int tid = threadIdx.x;
    const int lane = tid & 31, wid = tid >> 5;
    const int g = lane >> 2, t = lane & 3;
    const int wm = wid >> 2, wn = wid & 3;
    const int rm = wm * 64, rn = wn * 32;
    const int m0 = blockIdx.y * 128, n0 = blockIdx.x * 128;

    const int frow = tid >> 3, fcol = (tid & 7) * 8;   // 32 rows per pass
    const bf16* Ag = A + (size_t)m0 * lda + fcol;
    const bf16* Bg = B + (size_t)n0 * ldb + fcol;

    float acc[4][4][4];
#pragma unroll
    for (int a = 0; a < 4; a++)
#pragma unroll
        for (int b = 0; b < 4; b++)
#pragma unroll
            for (int c = 0; c < 4; c++) acc[a][b][c] = 0.f;

    const int nk = K / 64;
    // prologue: tiles 0 and 1
#pragma unroll
    for (int r = 0; r < 4; r++) {
        int row = frow + 32 * r;
        cpasync16(sptr(&As[row * 72 + fcol]), Ag + (size_t)row * lda);
        cpasync16(sptr(&Bs[row * 72 + fcol]), Bg + (size_t)row * ldb);
    }
    cpcommit();
    if (nk > 1) {
#pragma unroll
        for (int r = 0; r < 4; r++) {
            int row = frow + 32 * r;
            cpasync16(sptr(&As[9216 + row * 72 + fcol]),
                      Ag + (size_t)row * lda + 64);
            cpasync16(sptr(&Bs[9216 + row * 72 + fcol]),
                      Bg + (size_t)row * ldb + 64);
        }
    }
    cpcommit();

    for (int kt = 0; kt < nk; kt++) {
        const int buf = kt & 1;
        if (kt + 1 < nk) cpwaitg<1>(); else cpwaitg<0>();
        __syncthreads();

        const unsigned Abase = sptr(&As[buf * 9216]) +
            ((rm + (lane & 15)) * 72 + (lane >> 4) * 8) * 2;
        // x4 B loads: 4 matrices at +0/+16/+32/+48 B = k0..31
        const unsigned Bbase4 = sptr(&Bs[buf * 9216]) +
            ((rn + (lane & 7)) * 72) * 2 + (lane >> 3) * 16;

#pragma unroll
        for (int ksp = 0; ksp < 2; ksp++) {      // two k32 halves
            unsigned afr[2][4][4];
#pragma unroll
            for (int h2 = 0; h2 < 2; h2++)        // two k16 within half
#pragma unroll
                for (int mf = 0; mf < 4; mf++)
                    ldsm4(afr[h2][mf],
                          Abase + mf * 2304 + (ksp * 2 + h2) * 32);
#pragma unroll
            for (int nf = 0; nf < 4; nf++) {
                unsigned kf[4];
                ldsm4(kf, Bbase4 + nf * 1152 + ksp * 64);
#pragma unroll
                for (int mf = 0; mf < 4; mf++) {
                    mma16816(acc[mf][nf], afr[0][mf], kf[0], kf[1]);
                    mma16816(acc[mf][nf], afr[1][mf], kf[2], kf[3]);
                }
            }
        }
        __syncthreads();
        if (kt + 2 < nk) {
            const int ko = (kt + 2) * 64;
#pragma unroll
            for (int r = 0; r < 4; r++) {
                int row = frow + 32 * r;
                cpasync16(sptr(&As[buf * 9216 + row * 72 + fcol]),
                          Ag + (size_t)row * lda + ko);
                cpasync16(sptr(&Bs[buf * 9216 + row * 72 + fcol]),
                          Bg + (size_t)row * ldb + ko);
            }
        }
        cpcommit();
    }

#pragma unroll
    for (int mf = 0; mf < 4; mf++) {
        const int m = m0 + rm + mf * 16 + g;
#pragma unroll
        for (int nf = 0; nf < 4; nf++) {
            const int n = n0 + rn + nf * 8 + 2 * t;
            float2 bb = *(const float2*)&bias[n];
            float v0 = acc[mf][nf][0] + bb.x;
            float v1 = acc[mf][nf][1] + bb.y;
            float v2 = acc[mf][nf][2] + bb.x;
            float v3 = acc[mf][nf][3] + bb.y;
            if (doScale) {
                const float sc = 0.18033688f * wcq[(n & (NODE - 1)) >> 6];
                v0 *= sc; v1 *= sc; v2 *= sc; v3 *= sc;
            }
            if (Cf) {
                float2 r0 = *(const float2*)&resid[(size_t)m * ldr + n];
                float2 r1 = *(const float2*)&resid[(size_t)(m + 8) * ldr + n];
                *(float2*)&Cf[(size_t)m * ldc + n] = make_float2(v0 + r0.x, v1 + r0.y);
                *(float2*)&Cf[(size_t)(m + 8) * ldc + n] = make_float2(v2 + r1.x, v3 + r1.y);
            } else {
                *(unsigned*)&Cb[(size_t)m * ldc + n] = pack_bf16(v0, v1);
                *(unsigned*)&Cb[(size_t)(m + 8) * ldc + n] = pack_bf16(v2, v3);
            }
        }
    }
}

// ---------------------------------------------------------------------------
// Flash attention (R13, unchanged): 128 q-rows/CTA, 4 warps x 32 rows,
// no-max softmax (scale pre-folded into Q), chunked QK->exp->PV with x4
// ldsm batching, contact/K/V staged via cp.async 2-stage rings.
// grid = (NH, S/128), block = 128.
// ---------------------------------------------------------------------------
__global__ __launch_bounds__(128, 2)
void attn_mma(const bf16* __restrict__ qkv,
              const bf16* __restrict__ contact,
              bf16* __restrict__ O)
{
    extern __shared__ bf16 sm[];
    bf16* Qs = sm;                       // [128][72]
    bf16* KVs = sm + 9216;               // [2 stage][K|V][64*72]
    bf16* Cs = sm + 9216 + 18432;        // [2 stage][128][72]

    const int tid = threadIdx.x;
    const int lane = tid & 31, wid = tid >> 5;
    const int g = lane >> 2, t = lane & 3;
    const int h = blockIdx.x;
    const int q0 = blockIdx.y * 128;
    const int wr0 = wid * 32;

    const bf16* Qp = qkv;
    const bf16* Kp = qkv + (size_t)S_LEN * NODE;
    const bf16* Vp = qkv + 2 * (size_t)S_LEN * NODE;

    const int frow = tid >> 3, fcol = (tid & 7) * 8;

    // ---- prologue: Q + C(0) + KV(0), one group ----
#pragma unroll
    for (int r = 0; r < 8; r++) {
        int row = frow + 16 * r;
        cpasync16(sptr(&Qs[row * 72 + fcol]),
                  &Qp[(size_t)(q0 + row) * NODE + h * HD + fcol]);
        cpasync16(sptr(&Cs[row * 72 + fcol]),
                  &contact[(size_t)(q0 + row) * S_LEN + fcol]);
    }
#pragma unroll
    for (int r = 0; r < 4; r++) {
        int row = frow + 16 * r;
        cpasync16(sptr(&KVs[row * 72 + fcol]),
                  &Kp[(size_t)row * NODE + h * HD + fcol]);
        cpasync16(sptr(&KVs[4608 + row * 72 + fcol]),
                  &Vp[(size_t)row * NODE + h * HD + fcol]);
    }
    cpcommit();
    cpwaitg<0>();
    __syncthreads();

    // ---- hoist Q fragments ----
    unsigned qf[2][4][4];
#pragma unroll
    for (int mt = 0; mt < 2; mt++) {
        const unsigned qa = sptr(Qs) +
            ((wr0 + mt * 16 + (lane & 15)) * 72 + (lane >> 4) * 8) * 2;
#pragma unroll
        for (int ks = 0; ks < 4; ks++)
            ldsm4(qf[mt][ks], qa + ks * 32);
    }

    float oc[2][8][4];
#pragma unroll
    for (int mt = 0; mt < 2; mt++)
#pragma unroll
        for (int nf = 0; nf < 8; nf++)
#pragma unroll
            for (int j = 0; j < 4; j++) oc[mt][nf][j] = 0.f;
    float lacc[2][2] = {{0.f, 0.f}, {0.f, 0.f}};

    for (int kb = 0; kb < NKB; kb++) {
        const int buf = kb & 1;
        if (kb > 0) {
            cpwaitg<0>();
            __syncthreads();
        }

        // distance-1 prefetch: C(kb+1) + KV(kb+1) into the other stage
        if (kb + 1 < NKB) {
            const int nb = buf ^ 1;
            const size_t gr = (size_t)(kb + 1) * 64;
            bf16* dK = KVs + nb * 9216;
            bf16* dC = Cs + nb * 9216;
#pragma unroll
            for (int r = 0; r < 8; r++) {
                int row = frow + 16 * r;
                cpasync16(sptr(&dC[row * 72 + fcol]),
                          &contact[(size_t)(q0 + row) * S_LEN + gr + fcol]);
            }
#pragma unroll
            for (int r = 0; r < 4; r++) {
                int row = frow + 16 * r;
                cpasync16(sptr(&dK[row * 72 + fcol]),
                          &Kp[(gr + row) * NODE + h * HD + fcol]);
                cpasync16(sptr(&dK[4608 + row * 72 + fcol]),
                          &Vp[(gr + row) * NODE + h * HD + fcol]);
            }
        }
        cpcommit();

        const bf16* Kb = KVs + buf * 9216;
        const unsigned kAddr4 = sptr(Kb) +
            ((lane & 7) * 72) * 2 + (lane >> 3) * 16;
        const unsigned vAddr4 = sptr(Kb + 4608) +
            ((lane & 15) * 72) * 2 + (lane >> 4) * 16;
        const bf16* Cb = Cs + buf * 9216;

        // ---- 4 chunks of 16 keys: QK -> exp -> PV ----
#pragma unroll
        for (int ch = 0; ch < 4; ch++) {
            const int n0 = 2 * ch;
            unsigned cu[4][2];
#pragma unroll
            for (int i = 0; i < 4; i++) {
                const bf16* crp = Cb + (wr0 + g + 8 * i) * 72 + 2 * t;
#pragma unroll
                for (int j = 0; j < 2; j++)
                    cu[i][j] = *(const unsigned*)&crp[(n0 + j) * 8];
            }

            float s[2][2][4];
#pragma unroll
            for (int j = 0; j < 2; j++) {
                unsigned kf[8];
                ldsm4(kf, kAddr4 + (n0 + j) * 1152);
                ldsm4(kf + 4, kAddr4 + (n0 + j) * 1152 + 64);
#pragma unroll
                for (int q = 0; q < 4; q++) {
                    s[0][j][q] = 0.f;
                    s[1][j][q] = 0.f;
                }
#pragma unroll
                for (int ks = 0; ks < 4; ks++) {
                    mma16816(s[0][j], qf[0][ks], kf[2 * ks], kf[2 * ks + 1]);
                    mma16816(s[1][j], qf[1][ks], kf[2 * ks], kf[2 * ks + 1]);
                }
            }

            unsigned apk[2][4];
#pragma unroll
            for (int mt = 0; mt < 2; mt++) {
#pragma unroll
                for (int j = 0; j < 2; j++) {
                    float2 cf0 = __bfloat1622float2(
                        *(const bf162*)&cu[2 * mt][j]);
                    float2 cf1 = __bfloat1622float2(
                        *(const bf162*)&cu[2 * mt + 1][j]);
                    float e0 = ex2(s[mt][j][0] * cf0.x);
                    float e1 = ex2(s[mt][j][1] * cf0.y);
                    float e2 = ex2(s[mt][j][2] * cf1.x);
                    float e3 = ex2(s[mt][j][3] * cf1.y);
                    lacc[mt][0] += e0 + e1;
                    lacc[mt][1] += e2 + e3;
                    apk[mt][2 * j] = pack_bf16(e0, e1);
                    apk[mt][2 * j + 1] = pack_bf16(e2, e3);
                }
            }

#pragma unroll
            for (int nfp = 0; nfp < 4; nfp++) {
                unsigned vf[4];
                ldsm4t(vf, vAddr4 + ch * 2304 + nfp * 32);
                mma16816(oc[0][2 * nfp], apk[0], vf[0], vf[1]);
                mma16816(oc[1][2 * nfp], apk[1], vf[0], vf[1]);
                mma16816(oc[0][2 * nfp + 1], apk[0], vf[2], vf[3]);
                mma16816(oc[1][2 * nfp + 1], apk[1], vf[2], vf[3]);
            }
        }
    }

    // ---- normalize + store flat [H][S][D] bf16 ----
#pragma unroll
    for (int mt = 0; mt < 2; mt++) {
        float la = lacc[mt][0], lb = lacc[mt][1];
        la += __shfl_xor_sync(0xffffffffu, la, 1);
        la += __shfl_xor_sync(0xffffffffu, la, 2);
        lb += __shfl_xor_sync(0xffffffffu, lb, 1);
        lb += __shfl_xor_sync(0xffffffffu, lb, 2);
        const float inv0 = 1.f / la;
        const float inv1 = 1.f / lb;
        bf16* dst0 = O + (size_t)h * S_LEN * HD +
                     (size_t)(q0 + wr0 + mt * 16 + g) * HD;
        bf16* dst1 = dst0 + 8 * HD;
#pragma unroll
        for (int nf = 0; nf < 8; nf++) {
            int col = nf * 8 + 2 * t;
            *(unsigned*)&dst0[col] =
                pack_bf16(oc[mt][nf][0] * inv0, oc[mt][nf][1] * inv0);
            *(unsigned*)&dst1[col] =
                pack_bf16(oc[mt][nf][2] * inv1, oc[mt][nf][3] * inv1);
        }
    }
}

// ---------------------------------------------------------------------------
// LayerNorm: 2 rows per block, 128 threads/row (4 warps/row), float4.
// ---------------------------------------------------------------------------
__global__ __launch_bounds__(256)
void ln_kernel(const float* __restrict__ x,
               const float* __restrict__ gamma,
               const float* __restrict__ beta,
               float* __restrict__ out)
{
    __shared__ float red[8];
    __shared__ float red2[8];
    const int tid = threadIdx.x;
    const int rsel = tid >> 7;                 // 0 or 1
    const int row = blockIdx.x * 2 + rsel;
    const int c4 = (tid & 127) * 4;
    const int wid = tid >> 5;                  // 0..7 (warps 0-3 row0, 4-7 row1)
    const float* xr = x + (size_t)row * NODE;
    float4 v = *(const float4*)&xr[c4];

    float ssum = v.x + v.y + v.z + v.w;
#pragma unroll
    for (int off = 16; off >= 1; off >>= 1)
        ssum += __shfl_xor_sync(0xffffffffu, ssum, off);
    if ((tid & 31) == 0) red[wid] = ssum;
    __syncthreads();
    const float mean = (red[4 * rsel + 0] + red[4 * rsel + 1] +
                        red[4 * rsel + 2] + red[4 * rsel + 3]) * (1.f / NODE);

    const float dx = v.x - mean, dy = v.y - mean;
    const float dz = v.z - mean, dw = v.w - mean;
    float sq = dx * dx + dy * dy + dz * dz + dw * dw;
#pragma unroll
    for (int off = 16; off >= 1; off >>= 1)
        sq += __shfl_xor_sync(0xffffffffu, sq, off);
    if ((tid & 31) == 0) red2[wid] = sq;
    __syncthreads();
    const float inv = rsqrtf((red2[4 * rsel + 0] + red2[4 * rsel + 1] +
                              red2[4 * rsel + 2] + red2[4 * rsel + 3]) *
                             (1.f / NODE) + 1e-5f);

    float4 gm = *(const float4*)&gamma[c4];
    float4 bt = *(const float4*)&beta[c4];
    float4 o;
    o.x = dx * inv * gm.x + bt.x;
    o.y = dy * inv * gm.y + bt.y;
    o.z = dz * inv * gm.z + bt.z;
    o.w = dw * inv * gm.w + bt.w;
    *(float4*)&out[(size_t)row * NODE + c4] = o;
}

// ---------------------------------------------------------------------------
extern "C" void kernel_launch(void* const* d_in, const int* in_sizes, int n_in,
                              void* d_out, int out_size)
{
    const float* X     = (const float*)d_in[0];
    const float* Ct    = (const float*)d_in[1];
    const float* Wq    = (const float*)d_in[2];
    const float* bq    = (const float*)d_in[3];
    const float* Wk    = (const float*)d_in[4];
    const float* bk    = (const float*)d_in[5];
    const float* Wv    = (const float*)d_in[6];
    const float* bv    = (const float*)d_in[7];
    const float* Wc    = (const float*)d_in[8];
    const float* Wo    = (const float*)d_in[9];
    const float* bo    = (const float*)d_in[10];
    const float* gamma = (const float*)d_in[11];
    const float* beta  = (const float*)d_in[12];
    float* out = (float*)d_out;

    void *pX, *pWq, *pWk, *pWv, *pWo, *pC, *pQKV, *pO, *pAug;
    cudaGetSymbolAddress(&pX, g_Xbf);
    cudaGetSymbolAddress(&pWq, g_Wqb);
    cudaGetSymbolAddress(&pWk, g_Wkb);
    cudaGetSymbolAddress(&pWv, g_Wvb);
    cudaGetSymbolAddress(&pWo, g_Wob);
    cudaGetSymbolAddress(&pC, g_Cbf);
    cudaGetSymbolAddress(&pQKV, g_QKVb);
    cudaGetSymbolAddress(&pO, g_Obf);
    cudaGetSymbolAddress(&pAug, g_aug);
    bf16* Xbf = (bf16*)pX;
    bf16* Wqb = (bf16*)pWq;
    bf16* Wkb = (bf16*)pWk;
    bf16* Wvb = (bf16*)pWv;
    bf16* Wob = (bf16*)pWo;
    bf16* Cbf = (bf16*)pC;
    bf16* qkv = (bf16*)pQKV;
    bf16* Obf = (bf16*)pO;
    float* aug = (float*)pAug;

    const int gemm_smem = 2 * 2 * 128 * 72 * (int)sizeof(bf16);   // 73728
    cudaFuncSetAttribute(gemm_bf16,
                         cudaFuncAttributeMaxDynamicSharedMemorySize,
                         gemm_smem);
    const int attn_smem = (9216 + 18432 + 18432) * (int)sizeof(bf16); // 92160
    cudaFuncSetAttribute(attn_mma,
                         cudaFuncAttributeMaxDynamicSharedMemorySize,
                         attn_smem);

    // 1. fp32 -> bf16 (contact, X, weights), 4-way ILP
    cvt_all<<<5568, 256>>>(Ct, X, Wq, Wk, Wv, Wo,
                           Cbf, Xbf, Wqb, Wkb, Wvb, Wob);

    // 2. fused QKV projection (Q scaled by per-head attn scale)
    gemm_bf16<<<dim3(NODE / 128, S_LEN / 128, 3), 256, gemm_smem>>>(
        Xbf, IN_DIM, Wqb, Wkb, Wvb, IN_DIM, IN_DIM,
        bq, bk, bv, nullptr, 0, nullptr,
        qkv, qkv + (size_t)S_LEN * NODE, qkv + 2 * (size_t)S_LEN * NODE, NODE,
        Wc);

    // 3. flash attention (R13, unchanged)
    attn_mma<<<dim3(NH, S_LEN / 128), 128, attn_smem>>>(qkv, Cbf, Obf);

    // 4. output projection + bias + residual
    gemm_bf16<<<dim3(NODE / 128, S_LEN / 128, 1), 256, gemm_smem>>>(
        Obf, NODE, Wob, Wob, Wob, NODE, NODE,
        bo, bo, bo, X, IN_DIM, aug,
        nullptr, nullptr, nullptr, NODE, nullptr);

    // 5. LayerNorm (2 rows/block, 4 warps/row, float4)
    ln_kernel<<<S_LEN / 2, 256>>>(aug, gamma, beta, out);
}